// round 13
// baseline (speedup 1.0000x reference)
#include <cuda_runtime.h>
#include <cuda_fp16.h>
#include <cstdint>

#define OUT_F 2048
#define IN_F  2048
#define NNZ   209715
#define T_TOK 16384

// ---------------------------------------------------------------------------
// Scratch: fp16 copies of X and reconstructed W.
// ---------------------------------------------------------------------------
__device__ __half g_Wh[OUT_F * IN_F];           //  8 MB
__device__ __half g_Xh[(size_t)T_TOK * IN_F];   // 64 MB
__device__ unsigned g_dq_done;                  // dequant-blocks-finished counter

__device__ __forceinline__ uint32_t smem_u32(const void* p) {
    uint32_t a;
    asm("{ .reg .u64 t; cvta.to.shared.u64 t, %1; cvt.u32.u64 %0, t; }"
        : "=r"(a) : "l"(p));
    return a;
}

#define CP_ASYNC16(dst, src) \
    asm volatile("cp.async.cg.shared.global [%0], [%1], 16;" \
                 :: "r"((uint32_t)(dst)), "l"(src) : "memory")
#define CP_COMMIT() asm volatile("cp.async.commit_group;" ::: "memory")
#define CP_WAITN(n) asm volatile("cp.async.wait_group %0;" :: "n"(n) : "memory")

// SW128 swizzle on byte offsets (128B rows, 1024B atoms)
#define SWZ(o) ((o) ^ (((o) >> 3) & 0x70))

__device__ __forceinline__ void ldmatrix_x4(uint32_t* r, uint32_t addr) {
    asm volatile("ldmatrix.sync.aligned.m8n8.x4.shared.b16 {%0,%1,%2,%3}, [%4];"
                 : "=r"(r[0]), "=r"(r[1]), "=r"(r[2]), "=r"(r[3]) : "r"(addr));
}

__device__ __forceinline__ void mma_16816(float* c, const uint32_t* a,
                                          const uint32_t* b) {
    asm volatile(
        "mma.sync.aligned.m16n8k16.row.col.f32.f16.f16.f32 "
        "{%0,%1,%2,%3}, {%4,%5,%6,%7}, {%8,%9}, {%0,%1,%2,%3};"
        : "+f"(c[0]), "+f"(c[1]), "+f"(c[2]), "+f"(c[3])
        : "r"(a[0]), "r"(a[1]), "r"(a[2]), "r"(a[3]), "r"(b[0]), "r"(b[1]));
}

// ---------------------------------------------------------------------------
// Kernel 1 (fused prep, R10-proven): grid = [dequant | cvtx | scatter].
// ---------------------------------------------------------------------------
#define DQ_N4     (OUT_F * (IN_F / 2) / 4)     // 524288 int4-groups
#define DQ_BLOCKS (DQ_N4 / 256)                // 2048
#define CV_N      ((T_TOK * IN_F) / 4)         // 8388608 float4s
#define CV_BLOCKS (CV_N / 256)                 // 32768
#define SC_BLOCKS ((NNZ + 255) / 256)          // 820

__global__ void prep_kernel(const int* __restrict__ packed,
                            const float* __restrict__ scales,
                            const float* __restrict__ x,
                            const float* __restrict__ vals,
                            const int* __restrict__ rows,
                            const int* __restrict__ cols) {
    if (blockIdx.x < DQ_BLOCKS) {
        int idx = blockIdx.x * 256 + threadIdx.x;          // int4-group index
        int o = idx >> 8;                                  // / (IN_F/8)
        int4 v = reinterpret_cast<const int4*>(packed)[idx];
        float s = scales[o];
        __half2 h[4];
        h[0] = __floats2half2_rn((float)((v.x & 0xF) - 8) * s,
                                 (float)(((v.x >> 4) & 0xF) - 8) * s);
        h[1] = __floats2half2_rn((float)((v.y & 0xF) - 8) * s,
                                 (float)(((v.y >> 4) & 0xF) - 8) * s);
        h[2] = __floats2half2_rn((float)((v.z & 0xF) - 8) * s,
                                 (float)(((v.z >> 4) & 0xF) - 8) * s);
        h[3] = __floats2half2_rn((float)((v.w & 0xF) - 8) * s,
                                 (float)(((v.w >> 4) & 0xF) - 8) * s);
        reinterpret_cast<uint4*>(g_Wh)[idx] = *reinterpret_cast<uint4*>(h);
        __syncthreads();
        if (threadIdx.x == 0) {
            __threadfence();
            atomicAdd(&g_dq_done, 1u);
        }
    } else if (blockIdx.x < DQ_BLOCKS + CV_BLOCKS) {
        int i = (blockIdx.x - DQ_BLOCKS) * 256 + threadIdx.x;
        float4 v = reinterpret_cast<const float4*>(x)[i];
        reinterpret_cast<__half2*>(g_Xh)[2 * i]     = __floats2half2_rn(v.x, v.y);
        reinterpret_cast<__half2*>(g_Xh)[2 * i + 1] = __floats2half2_rn(v.z, v.w);
    } else {
        if (threadIdx.x == 0) {
            volatile unsigned* flag = &g_dq_done;
            while (*flag < DQ_BLOCKS) {
                asm volatile("nanosleep.u32 64;");
            }
        }
        __syncthreads();
        __threadfence();
        int i = (blockIdx.x - DQ_BLOCKS - CV_BLOCKS) * 256 + threadIdx.x;
        if (i < NNZ)
            atomicAdd(&g_Wh[(size_t)rows[i] * IN_F + cols[i]],
                      __float2half(vals[i]));
    }
}

// ---------------------------------------------------------------------------
// Kernel 2: fp16 HMMA GEMM.  CTA 128x128, BK=128, 2-stage cp.async,
// 4 warps of 64x64, register double-buffered fragments.
// BK=128 halves the iteration count (32 -> 16): the ~350 cyc/iter fixed
// overhead (wait + barrier + un-overlapped first frag load) measured in
// R9/R10 amortizes over 2048 MMA cycles instead of 1024.
// Each operand stage is stored as TWO 128-byte-wide K-panels so the proven
// SW128 swizzle / ldmatrix addressing is unchanged within a panel.
// ---------------------------------------------------------------------------
#define MT 128
#define NT 128
#define BK 128
#define NSTAGE 2
#define PANEL_BYTES 16384u                     // 128 rows x 128B
#define STAGE_BYTES 65536u                     // A 2 panels + B 2 panels
#define A_OFF(s) ((s) * STAGE_BYTES)
#define B_OFF(s) (A_OFF(s) + 32768u)
#define GEMM_SMEM (NSTAGE * STAGE_BYTES)       // 131072

__device__ __forceinline__ void load_stage(uint32_t sb, int tid,
                                           const __half* Xb, const __half* Wb,
                                           int k0, int s) {
    // A: 128 rows x 16 chunks(16B) = 2048 chunks, 16 per thread (128 thr)
    #pragma unroll
    for (int j = 0; j < 16; j++) {
        int item = tid + j * 128;
        int row = item >> 4, ck = item & 15;
        int panel = ck >> 3, ckl = ck & 7;
        CP_ASYNC16(sb + A_OFF(s) + panel * PANEL_BYTES + SWZ(row * 128 + ckl * 16),
                   Xb + (size_t)row * IN_F + k0 + ck * 8);
    }
    // B: same shape
    #pragma unroll
    for (int j = 0; j < 16; j++) {
        int item = tid + j * 128;
        int row = item >> 4, ck = item & 15;
        int panel = ck >> 3, ckl = ck & 7;
        CP_ASYNC16(sb + B_OFF(s) + panel * PANEL_BYTES + SWZ(row * 128 + ckl * 16),
                   Wb + (size_t)row * IN_F + k0 + ck * 8);
    }
    CP_COMMIT();
}

// Fragments for k16-step kslot (0..7) of a 64x64 warp tile.
__device__ __forceinline__ void load_frags(uint32_t sA, uint32_t sB,
                                           int wm, int wn, int lane, int kslot,
                                           uint32_t af[4][4], uint32_t bf[8][2]) {
    const uint32_t pA = sA + (kslot >> 2) * PANEL_BYTES;
    const uint32_t pB = sB + (kslot >> 2) * PANEL_BYTES;
    const int ckb = (kslot & 3) * 2;
    #pragma unroll
    for (int mt = 0; mt < 4; mt++) {
        int row = wm + mt * 16 + (lane & 7) + ((lane >> 3) & 1) * 8;
        int ck  = ckb + ((lane >> 4) & 1);
        ldmatrix_x4(af[mt], pA + SWZ(row * 128 + ck * 16));
    }
    #pragma unroll
    for (int np = 0; np < 4; np++) {
        int sel = lane >> 3;
        int row = wn + np * 16 + (sel >> 1) * 8 + (lane & 7);
        int ck  = ckb + (sel & 1);
        uint32_t r[4];
        ldmatrix_x4(r, pB + SWZ(row * 128 + ck * 16));
        bf[np * 2 + 0][0] = r[0]; bf[np * 2 + 0][1] = r[1];
        bf[np * 2 + 1][0] = r[2]; bf[np * 2 + 1][1] = r[3];
    }
}

__global__ __launch_bounds__(128, 1) void gemm_hmma(float* __restrict__ C) {
    extern __shared__ char smem[];
    const uint32_t sb = smem_u32(smem);
    const int tid  = threadIdx.x;
    const int wid  = tid >> 5;
    const int lane = tid & 31;

    if (blockIdx.x == 0 && blockIdx.y == 0 && tid == 0) g_dq_done = 0;

    const int m0 = blockIdx.y * MT;
    const int n0 = blockIdx.x * NT;
    const int wm = (wid & 1) * 64;
    const int wn = (wid >> 1) * 64;

    const __half* Xb = g_Xh + (size_t)m0 * IN_F;
    const __half* Wb = g_Wh + (size_t)n0 * IN_F;

    float acc[4][8][4];
    #pragma unroll
    for (int i = 0; i < 4; i++)
        #pragma unroll
        for (int j = 0; j < 8; j++)
            #pragma unroll
            for (int q = 0; q < 4; q++) acc[i][j][q] = 0.0f;

    load_stage(sb, tid, Xb, Wb, 0, 0);

    uint32_t af[2][4][4];
    uint32_t bf[2][8][2];

    const int NIT = IN_F / BK;   // 16
    for (int k = 0; k < NIT; k++) {
        CP_WAITN(0);             // stage k (issued at iter k-1) complete
        __syncthreads();         // visible to all; buffer (k+1)&1 reusable

        if (k + 1 < NIT)
            load_stage(sb, tid, Xb, Wb, (k + 1) * BK, (k + 1) & 1);

        const uint32_t sA = sb + A_OFF(k & 1);
        const uint32_t sB = sb + B_OFF(k & 1);

        load_frags(sA, sB, wm, wn, lane, 0, af[0], bf[0]);

        #pragma unroll
        for (int ks = 0; ks < BK / 16; ks++) {   // 8 k16-steps
            const int cur = ks & 1;
            if (ks + 1 < BK / 16)
                load_frags(sA, sB, wm, wn, lane, ks + 1,
                           af[cur ^ 1], bf[cur ^ 1]);
            #pragma unroll
            for (int mt = 0; mt < 4; mt++)
                #pragma unroll
                for (int nt = 0; nt < 8; nt++)
                    mma_16816(acc[mt][nt], af[cur][mt], bf[cur][nt]);
        }
    }

    #pragma unroll
    for (int mt = 0; mt < 4; mt++) {
        #pragma unroll
        for (int nt = 0; nt < 8; nt++) {
            int m = m0 + wm + mt * 16 + (lane >> 2);
            int n = n0 + wn + nt * 8 + (lane & 3) * 2;
            float2* p0 = reinterpret_cast<float2*>(C + (size_t)m * OUT_F + n);
            float2* p1 = reinterpret_cast<float2*>(C + (size_t)(m + 8) * OUT_F + n);
            *p0 = make_float2(acc[mt][nt][0], acc[mt][nt][1]);
            *p1 = make_float2(acc[mt][nt][2], acc[mt][nt][3]);
        }
    }
}

// ---------------------------------------------------------------------------
// Launch: fused prep -> GEMM
// ---------------------------------------------------------------------------
extern "C" void kernel_launch(void* const* d_in, const int* in_sizes, int n_in,
                              void* d_out, int out_size) {
    const float* x      = (const float*)d_in[0];
    const int*   packed = (const int*)  d_in[1];
    const float* scales = (const float*)d_in[2];
    const float* o_vals = (const float*)d_in[3];
    const int*   o_rows = (const int*)  d_in[4];
    const int*   o_cols = (const int*)  d_in[5];
    float*       out    = (float*)d_out;

    cudaFuncSetAttribute(gemm_hmma,
                         cudaFuncAttributeMaxDynamicSharedMemorySize, GEMM_SMEM);

    prep_kernel<<<DQ_BLOCKS + CV_BLOCKS + SC_BLOCKS, 256>>>(
        packed, scales, x, o_vals, o_rows, o_cols);
    {
        dim3 grid(OUT_F / NT, T_TOK / MT);   // (16, 128)
        gemm_hmma<<<grid, 128, GEMM_SMEM>>>(out);
    }
}

// round 15
// speedup vs baseline: 1.2438x; 1.2438x over previous
#include <cuda_runtime.h>
#include <cuda_fp16.h>
#include <cstdint>

#define OUT_F 2048
#define IN_F  2048
#define NNZ   209715
#define T_TOK 16384

// ---------------------------------------------------------------------------
// Scratch: fp16 copies of X and reconstructed W.
// ---------------------------------------------------------------------------
__device__ __half g_Wh[OUT_F * IN_F];           //  8 MB
__device__ __half g_Xh[(size_t)T_TOK * IN_F];   // 64 MB
__device__ unsigned g_dq_done;                  // dequant-blocks-finished counter

__device__ __forceinline__ uint32_t smem_u32(const void* p) {
    uint32_t a;
    asm("{ .reg .u64 t; cvta.to.shared.u64 t, %1; cvt.u32.u64 %0, t; }"
        : "=r"(a) : "l"(p));
    return a;
}

#define CP_ASYNC16(dst, src) \
    asm volatile("cp.async.cg.shared.global [%0], [%1], 16;" \
                 :: "r"((uint32_t)(dst)), "l"(src) : "memory")
#define CP_COMMIT() asm volatile("cp.async.commit_group;" ::: "memory")
#define CP_WAITN(n) asm volatile("cp.async.wait_group %0;" :: "n"(n) : "memory")

// SW128 swizzle on byte offsets (128B rows, 1024B atoms)
#define SWZ(o) ((o) ^ (((o) >> 3) & 0x70))

__device__ __forceinline__ void ldmatrix_x4(uint32_t* r, uint32_t addr) {
    asm volatile("ldmatrix.sync.aligned.m8n8.x4.shared.b16 {%0,%1,%2,%3}, [%4];"
                 : "=r"(r[0]), "=r"(r[1]), "=r"(r[2]), "=r"(r[3]) : "r"(addr));
}

__device__ __forceinline__ void mma_16816(float* c, const uint32_t* a,
                                          const uint32_t* b) {
    asm volatile(
        "mma.sync.aligned.m16n8k16.row.col.f32.f16.f16.f32 "
        "{%0,%1,%2,%3}, {%4,%5,%6,%7}, {%8,%9}, {%0,%1,%2,%3};"
        : "+f"(c[0]), "+f"(c[1]), "+f"(c[2]), "+f"(c[3])
        : "r"(a[0]), "r"(a[1]), "r"(a[2]), "r"(a[3]), "r"(b[0]), "r"(b[1]));
}

__device__ __forceinline__ void stcs128(void* p, uint4 v) {
    asm volatile("st.global.cs.v4.b32 [%0], {%1,%2,%3,%4};"
                 :: "l"(p), "r"(v.x), "r"(v.y), "r"(v.z), "r"(v.w) : "memory");
}

// ---------------------------------------------------------------------------
// Kernel 1 (fused prep): grid = [dequant | cvtx | scatter].
// cvt blocks: 1024 float4 in -> 512 uint4 out per block (each 16B store
// consumes TWO float4s = 8 floats -> 8 halfs), streaming stores.
// ---------------------------------------------------------------------------
#define DQ_N4     (OUT_F * (IN_F / 2) / 4)     // 524288 int4-groups
#define DQ_BLOCKS (DQ_N4 / 256)                // 2048
#define CV_N      ((T_TOK * IN_F) / 4)         // 8388608 float4s
#define CV_OUT    (CV_N / 2)                   // 4194304 uint4 outputs
#define CV_BLOCKS (CV_OUT / 512)               // 8192
#define SC_BLOCKS ((NNZ + 255) / 256)          // 820

__global__ void prep_kernel(const int* __restrict__ packed,
                            const float* __restrict__ scales,
                            const float* __restrict__ x,
                            const float* __restrict__ vals,
                            const int* __restrict__ rows,
                            const int* __restrict__ cols) {
    if (blockIdx.x < DQ_BLOCKS) {
        int idx = blockIdx.x * 256 + threadIdx.x;          // int4-group index
        int o = idx >> 8;                                  // / (IN_F/8)
        int4 v = reinterpret_cast<const int4*>(packed)[idx];
        float s = scales[o];
        __half2 h[4];
        h[0] = __floats2half2_rn((float)((v.x & 0xF) - 8) * s,
                                 (float)(((v.x >> 4) & 0xF) - 8) * s);
        h[1] = __floats2half2_rn((float)((v.y & 0xF) - 8) * s,
                                 (float)(((v.y >> 4) & 0xF) - 8) * s);
        h[2] = __floats2half2_rn((float)((v.z & 0xF) - 8) * s,
                                 (float)(((v.z >> 4) & 0xF) - 8) * s);
        h[3] = __floats2half2_rn((float)((v.w & 0xF) - 8) * s,
                                 (float)(((v.w >> 4) & 0xF) - 8) * s);
        reinterpret_cast<uint4*>(g_Wh)[idx] = *reinterpret_cast<uint4*>(h);
        __syncthreads();
        if (threadIdx.x == 0) {
            __threadfence();
            atomicAdd(&g_dq_done, 1u);
        }
    } else if (blockIdx.x < DQ_BLOCKS + CV_BLOCKS) {
        // Each output uint4 o consumes float4s 2o and 2o+1. 2 outputs/thread.
        int base = (blockIdx.x - DQ_BLOCKS) * 512 + threadIdx.x;
        #pragma unroll
        for (int j = 0; j < 2; j++) {
            int o = base + j * 256;                        // uint4 output idx
            float4 v0 = reinterpret_cast<const float4*>(x)[2 * o];
            float4 v1 = reinterpret_cast<const float4*>(x)[2 * o + 1];
            __half2 h[4];
            h[0] = __floats2half2_rn(v0.x, v0.y);
            h[1] = __floats2half2_rn(v0.z, v0.w);
            h[2] = __floats2half2_rn(v1.x, v1.y);
            h[3] = __floats2half2_rn(v1.z, v1.w);
            stcs128(reinterpret_cast<uint4*>(g_Xh) + o,
                    *reinterpret_cast<uint4*>(h));
        }
    } else {
        if (threadIdx.x == 0) {
            volatile unsigned* flag = &g_dq_done;
            while (*flag < DQ_BLOCKS) {
                asm volatile("nanosleep.u32 64;");
            }
        }
        __syncthreads();
        __threadfence();
        int i = (blockIdx.x - DQ_BLOCKS - CV_BLOCKS) * 256 + threadIdx.x;
        if (i < NNZ)
            atomicAdd(&g_Wh[(size_t)rows[i] * IN_F + cols[i]],
                      __float2half(vals[i]));
    }
}

// ---------------------------------------------------------------------------
// Kernel 2: fp16 HMMA GEMM (R9/R10 proven optimum — frozen).
// CTA 128x128, BK=64, 3-stage cp.async, 4 warps of 64x64,
// register double-buffered fragments.
// ---------------------------------------------------------------------------
#define MT 128
#define NT 128
#define BK 64
#define NSTAGE 3
#define STAGE_BYTES 32768u
#define A_OFF(s) ((s) * STAGE_BYTES)
#define B_OFF(s) (A_OFF(s) + 16384u)
#define GEMM_SMEM (NSTAGE * STAGE_BYTES)   // 98304

__device__ __forceinline__ void load_stage(uint32_t sb, int tid,
                                           const __half* Xb, const __half* Wb,
                                           int k0, int s) {
    #pragma unroll
    for (int j = 0; j < 8; j++) {
        int item = tid + j * 128;
        int row = item >> 3, ck = item & 7;
        CP_ASYNC16(sb + A_OFF(s) + SWZ(row * 128 + ck * 16),
                   Xb + (size_t)row * IN_F + k0 + ck * 8);
    }
    #pragma unroll
    for (int j = 0; j < 8; j++) {
        int item = tid + j * 128;
        int row = item >> 3, ck = item & 7;
        CP_ASYNC16(sb + B_OFF(s) + SWZ(row * 128 + ck * 16),
                   Wb + (size_t)row * IN_F + k0 + ck * 8);
    }
    CP_COMMIT();
}

__device__ __forceinline__ void load_frags(uint32_t sA, uint32_t sB,
                                           int wm, int wn, int lane, int kslot,
                                           uint32_t af[4][4], uint32_t bf[8][2]) {
    const int ckb = kslot * 2;
    #pragma unroll
    for (int mt = 0; mt < 4; mt++) {
        int row = wm + mt * 16 + (lane & 7) + ((lane >> 3) & 1) * 8;
        int ck  = ckb + ((lane >> 4) & 1);
        ldmatrix_x4(af[mt], sA + SWZ(row * 128 + ck * 16));
    }
    #pragma unroll
    for (int np = 0; np < 4; np++) {
        int sel = lane >> 3;
        int row = wn + np * 16 + (sel >> 1) * 8 + (lane & 7);
        int ck  = ckb + (sel & 1);
        uint32_t r[4];
        ldmatrix_x4(r, sB + SWZ(row * 128 + ck * 16));
        bf[np * 2 + 0][0] = r[0]; bf[np * 2 + 0][1] = r[1];
        bf[np * 2 + 1][0] = r[2]; bf[np * 2 + 1][1] = r[3];
    }
}

__global__ __launch_bounds__(128, 2) void gemm_hmma(float* __restrict__ C) {
    extern __shared__ char smem[];
    const uint32_t sb = smem_u32(smem);
    const int tid  = threadIdx.x;
    const int wid  = tid >> 5;
    const int lane = tid & 31;

    if (blockIdx.x == 0 && blockIdx.y == 0 && tid == 0) g_dq_done = 0;

    const int m0 = blockIdx.y * MT;
    const int n0 = blockIdx.x * NT;
    const int wm = (wid & 1) * 64;
    const int wn = (wid >> 1) * 64;

    const __half* Xb = g_Xh + (size_t)m0 * IN_F;
    const __half* Wb = g_Wh + (size_t)n0 * IN_F;

    float acc[4][8][4];
    #pragma unroll
    for (int i = 0; i < 4; i++)
        #pragma unroll
        for (int j = 0; j < 8; j++)
            #pragma unroll
            for (int q = 0; q < 4; q++) acc[i][j][q] = 0.0f;

    load_stage(sb, tid, Xb, Wb, 0, 0);
    load_stage(sb, tid, Xb, Wb, BK, 1);

    uint32_t af[2][4][4];
    uint32_t bf[2][8][2];

    const int NIT = IN_F / BK;   // 32
    for (int k = 0; k < NIT; k++) {
        if (k + 1 < NIT) CP_WAITN(1); else CP_WAITN(0);
        __syncthreads();

        if (k + 2 < NIT)
            load_stage(sb, tid, Xb, Wb, (k + 2) * BK, (k + 2) % NSTAGE);

        const int st = k % NSTAGE;
        const uint32_t sA = sb + A_OFF(st);
        const uint32_t sB = sb + B_OFF(st);

        load_frags(sA, sB, wm, wn, lane, 0, af[0], bf[0]);

        #pragma unroll
        for (int ks = 0; ks < BK / 16; ks++) {
            const int cur = ks & 1;
            if (ks + 1 < BK / 16)
                load_frags(sA, sB, wm, wn, lane, ks + 1,
                           af[cur ^ 1], bf[cur ^ 1]);
            #pragma unroll
            for (int mt = 0; mt < 4; mt++)
                #pragma unroll
                for (int nt = 0; nt < 8; nt++)
                    mma_16816(acc[mt][nt], af[cur][mt], bf[cur][nt]);
        }
    }

    #pragma unroll
    for (int mt = 0; mt < 4; mt++) {
        #pragma unroll
        for (int nt = 0; nt < 8; nt++) {
            int m = m0 + wm + mt * 16 + (lane >> 2);
            int n = n0 + wn + nt * 8 + (lane & 3) * 2;
            float2* p0 = reinterpret_cast<float2*>(C + (size_t)m * OUT_F + n);
            float2* p1 = reinterpret_cast<float2*>(C + (size_t)(m + 8) * OUT_F + n);
            *p0 = make_float2(acc[mt][nt][0], acc[mt][nt][1]);
            *p1 = make_float2(acc[mt][nt][2], acc[mt][nt][3]);
        }
    }
}

// ---------------------------------------------------------------------------
// Launch: fused prep -> GEMM
// ---------------------------------------------------------------------------
extern "C" void kernel_launch(void* const* d_in, const int* in_sizes, int n_in,
                              void* d_out, int out_size) {
    const float* x      = (const float*)d_in[0];
    const int*   packed = (const int*)  d_in[1];
    const float* scales = (const float*)d_in[2];
    const float* o_vals = (const float*)d_in[3];
    const int*   o_rows = (const int*)  d_in[4];
    const int*   o_cols = (const int*)  d_in[5];
    float*       out    = (float*)d_out;

    cudaFuncSetAttribute(gemm_hmma,
                         cudaFuncAttributeMaxDynamicSharedMemorySize, GEMM_SMEM);

    prep_kernel<<<DQ_BLOCKS + CV_BLOCKS + SC_BLOCKS, 256>>>(
        packed, scales, x, o_vals, o_rows, o_cols);
    {
        dim3 grid(OUT_F / NT, T_TOK / MT);   // (16, 128)
        gemm_hmma<<<grid, 128, GEMM_SMEM>>>(out);
    }
}